// round 14
// baseline (speedup 1.0000x reference)
#include <cuda_runtime.h>
#include <cuda_bf16.h>
#include <math.h>
#include <stdint.h>

#define M_TOK 16384
#define V_DIM 4096
#define C_DIM 128
#define K_NB2 128
#define N_OPS 8

// ------------------------- scratch (device globals) -------------------------
__device__ float g_rw[V_DIM * C_DIM];
__device__ __nv_bfloat16 g_rwTh[C_DIM * V_DIM];
__device__ __nv_bfloat16 g_rwTl[C_DIM * V_DIM];
__device__ __nv_bfloat16 g_wwh[V_DIM * C_DIM];
__device__ __nv_bfloat16 g_wwl[V_DIM * C_DIM];
__device__ __nv_bfloat16 g_wTh[N_OPS * C_DIM * C_DIM];
__device__ __nv_bfloat16 g_wTl[N_OPS * C_DIM * C_DIM];

// ------------------------- helpers -------------------------
__device__ __forceinline__ uint32_t smem_u32(const void* p) {
    uint32_t a;
    asm("{ .reg .u64 t; cvta.to.shared.u64 t, %1; cvt.u32.u64 %0, t; }" : "=r"(a) : "l"(p));
    return a;
}
#define CP16(saddr, gptr) \
    asm volatile("cp.async.cg.shared.global [%0], [%1], 16;" :: "r"(saddr), "l"(gptr) : "memory")
#define CP_COMMIT() asm volatile("cp.async.commit_group;" ::: "memory")
template <int N> __device__ __forceinline__ void cp_wait() {
    asm volatile("cp.async.wait_group %0;" :: "n"(N) : "memory");
}
#define BAR_SYNC(id, cnt) \
    asm volatile("bar.sync %0, %1;" :: "r"(id), "n"(cnt) : "memory")
#define BAR_ARRIVE(id, cnt) \
    asm volatile("bar.arrive %0, %1;" :: "r"(id), "n"(cnt) : "memory")
__device__ __forceinline__ void ldsm4(uint32_t& r0, uint32_t& r1, uint32_t& r2, uint32_t& r3, uint32_t a) {
    asm volatile("ldmatrix.sync.aligned.m8n8.x4.shared.b16 {%0,%1,%2,%3}, [%4];"
        : "=r"(r0), "=r"(r1), "=r"(r2), "=r"(r3) : "r"(a));
}
__device__ __forceinline__ void mma_bf16(float c[4], const uint32_t a[4], const uint32_t b[2]) {
    asm volatile(
        "mma.sync.aligned.m16n8k16.row.col.f32.bf16.bf16.f32 "
        "{%0,%1,%2,%3},{%4,%5,%6,%7},{%8,%9},{%0,%1,%2,%3};"
        : "+f"(c[0]), "+f"(c[1]), "+f"(c[2]), "+f"(c[3])
        : "r"(a[0]), "r"(a[1]), "r"(a[2]), "r"(a[3]), "r"(b[0]), "r"(b[1]));
}
__device__ __forceinline__ void split2(float a, float b, uint32_t& hi, uint32_t& lo) {
    __nv_bfloat16 ha = __float2bfloat16(a), hb = __float2bfloat16(b);
    __nv_bfloat16 la = __float2bfloat16(a - __bfloat162float(ha));
    __nv_bfloat16 lb = __float2bfloat16(b - __bfloat162float(hb));
    hi = (uint32_t)__bfloat16_as_ushort(ha) | ((uint32_t)__bfloat16_as_ushort(hb) << 16);
    lo = (uint32_t)__bfloat16_as_ushort(la) | ((uint32_t)__bfloat16_as_ushort(lb) << 16);
}
__device__ __forceinline__ void split1(float a, uint16_t& h, uint16_t& l) {
    __nv_bfloat16 ha = __float2bfloat16(a);
    __nv_bfloat16 la = __float2bfloat16(a - __bfloat162float(ha));
    h = __bfloat16_as_ushort(ha);
    l = __bfloat16_as_ushort(la);
}

// ---------------------------------------------------------------------------
// Addressing GEMM (fp32): scores = basis(4096x128) @ coeff^T
// ---------------------------------------------------------------------------
__global__ __launch_bounds__(256) void sgemm_addr(
    const float* __restrict__ A, const float* __restrict__ B0,
    const float* __restrict__ B1)
{
    __shared__ float As[16][128];
    __shared__ float Bs[16][128];
    const int tid = threadIdx.x;
    const int tc = tid % 16, tr = tid / 16;
    const int m0 = blockIdx.y * 128;
    const int path = blockIdx.z;
    const float* B = path ? B1 : B0;

    float acc[8][8];
#pragma unroll
    for (int i = 0; i < 8; i++)
#pragma unroll
        for (int j = 0; j < 8; j++) acc[i][j] = 0.0f;

    for (int k0 = 0; k0 < K_NB2; k0 += 16) {
#pragma unroll
        for (int i = 0; i < 2; i++) {
            int idx = tid + i * 256;
            int row = idx / 4, c4 = idx % 4;
            float4 va = *(const float4*)&A[(size_t)(m0 + row) * K_NB2 + k0 + c4 * 4];
            As[c4 * 4 + 0][row] = va.x; As[c4 * 4 + 1][row] = va.y;
            As[c4 * 4 + 2][row] = va.z; As[c4 * 4 + 3][row] = va.w;
            float4 vb = *(const float4*)&B[(size_t)row * K_NB2 + k0 + c4 * 4];
            Bs[c4 * 4 + 0][row] = vb.x; Bs[c4 * 4 + 1][row] = vb.y;
            Bs[c4 * 4 + 2][row] = vb.z; Bs[c4 * 4 + 3][row] = vb.w;
        }
        __syncthreads();
#pragma unroll
        for (int k = 0; k < 16; k++) {
            float ra[8], rb[8];
#pragma unroll
            for (int i = 0; i < 8; i++) ra[i] = As[k][tr * 8 + i];
#pragma unroll
            for (int j = 0; j < 8; j++) rb[j] = Bs[k][tc * 8 + j];
#pragma unroll
            for (int i = 0; i < 8; i++)
#pragma unroll
                for (int j = 0; j < 8; j++) acc[i][j] += ra[i] * rb[j];
        }
        __syncthreads();
    }
#pragma unroll
    for (int i = 0; i < 8; i++) {
        const size_t base = (size_t)(m0 + tr * 8 + i) * C_DIM + tc * 8;
        if (path == 0) {
#pragma unroll
            for (int j = 0; j < 8; j++) g_rw[base + j] = acc[i][j];
        } else {
#pragma unroll
            for (int j = 0; j < 8; j++) {
                uint16_t h, l;
                split1(acc[i][j], h, l);
                g_wwh[base + j] = __ushort_as_bfloat16(h);
                g_wwl[base + j] = __ushort_as_bfloat16(l);
            }
        }
    }
}

// ---------------------------------------------------------------------------
__global__ __launch_bounds__(256) void col_softmax_T(const float* __restrict__ S)
{
    __shared__ float col[V_DIM];
    __shared__ float red[256];
    const int c = blockIdx.x;
    const int tid = threadIdx.x;

    float m = -1e30f;
    for (int v = tid; v < V_DIM; v += 256) {
        float x = S[(size_t)v * C_DIM + c];
        col[v] = x;
        m = fmaxf(m, x);
    }
    red[tid] = m; __syncthreads();
    for (int s = 128; s > 0; s >>= 1) { if (tid < s) red[tid] = fmaxf(red[tid], red[tid + s]); __syncthreads(); }
    m = red[0]; __syncthreads();

    float sum = 0.0f;
    for (int v = tid; v < V_DIM; v += 256) { float e = expf(col[v] - m); col[v] = e; sum += e; }
    red[tid] = sum; __syncthreads();
    for (int s = 128; s > 0; s >>= 1) { if (tid < s) red[tid] += red[tid + s]; __syncthreads(); }
    const float inv = 1.0f / red[0];

    for (int v = tid; v < V_DIM; v += 256) {
        uint16_t h, l;
        split1(col[v] * inv, h, l);
        g_rwTh[(size_t)c * V_DIM + v] = __ushort_as_bfloat16(h);
        g_rwTl[(size_t)c * V_DIM + v] = __ushort_as_bfloat16(l);
    }
}

__global__ __launch_bounds__(256) void prep_wT(const float* __restrict__ W)
{
    int idx = blockIdx.x * 256 + threadIdx.x;
    int op = idx >> 14;
    int rem = idx & 16383;
    int n = rem >> 7, k = rem & 127;
    uint16_t h, l;
    split1(W[op * 16384 + k * 128 + n], h, l);
    g_wTh[idx] = __ushort_as_bfloat16(h);
    g_wTl[idx] = __ushort_as_bfloat16(l);
}

// ---------------------------------------------------------------------------
// MEGA: warp-specialized. 384 threads = 8 consumer warps (4x2, tile 32x64)
// + 4 producer warps. Two 64KB stages at [0,64K),[64K,128K):
//   phase1 stage: Ah 16K | Al 16K | Bh 16K | Bl 16K  (A=x-split, B=read_w^T)
//   phase2 stage: Wh(half) 16K | Wl 16K @ +16384
//   phase3 stage: WWh 32K | WWl 32K
// vals/mix: hi @128K, lo @160K (256B swizzled rows). Named barriers:
//   FULL[s]=1+s  EMPTY[s]=3+s  (384: 128 arrive + 256 sync); consumer-only id5 (256).
// ---------------------------------------------------------------------------
__global__ __launch_bounds__(384, 1) void mega(
    const float* __restrict__ x, const float* __restrict__ logits,
    const float* __restrict__ bias, float* __restrict__ out,
    const float* __restrict__ oscale)
{
    extern __shared__ char sm[];
    __shared__ float bs[N_OPS * C_DIM];
    const uint32_t sb = smem_u32(sm);
    const int tid = threadIdx.x, lane = tid & 31, wid = tid >> 5;
    const int m0 = blockIdx.x * 128;
    const uint32_t VH = 131072, VL = 163840;
    const bool producer = (wid >= 8);

    if (producer) {
        // ==================== PRODUCER PATH (warps 8-11) ====================
        const int ptid = tid - 256;           // 0..127
        const float* xbase = x + (size_t)m0 * V_DIM;
        float4 apf[16];

        auto ldA = [&](int k0) {
#pragma unroll
            for (int i = 0; i < 16; i++) {
                int idx = ptid + i * 128;
                apf[i] = *(const float4*)&xbase[(size_t)(idx >> 4) * V_DIM + k0 + (idx & 15) * 4];
            }
        };
        auto stA = [&](int s) {
            char* ah = sm + s * 65536;
            char* al = sm + s * 65536 + 16384;
#pragma unroll
            for (int i = 0; i < 16; i++) {
                int idx = ptid + i * 128;
                int r = idx >> 4, c4 = idx & 15;
                uint32_t h0, l0, h1, l1;
                split2(apf[i].x, apf[i].y, h0, l0);
                split2(apf[i].z, apf[i].w, h1, l1);
                uint32_t so = r * 128 + ((uint32_t)((c4 >> 1) ^ (r & 7)) << 4) + (c4 & 1) * 8;
                *(uint2*)(ah + so) = make_uint2(h0, h1);
                *(uint2*)(al + so) = make_uint2(l0, l1);
            }
        };
        auto ldB = [&](int k0, int s) {
            uint32_t bh = sb + s * 65536 + 32768;
            uint32_t bl = bh + 16384;
#pragma unroll
            for (int i = 0; i < 8; i++) {
                int idx = ptid + i * 128;
                int r = idx >> 3, c = idx & 7;
                uint32_t so = r * 128 + ((uint32_t)(c ^ (r & 7)) << 4);
                CP16(bh + so, &g_rwTh[(size_t)r * V_DIM + k0 + c * 8]);
                CP16(bl + so, &g_rwTl[(size_t)r * V_DIM + k0 + c * 8]);
            }
        };

        // -------- phase 1 --------
        ldA(0);
        for (int ch = 0; ch < 64; ch++) {
            const int s = ch & 1;
            if (ch >= 2) BAR_SYNC(3 + s, 384);
            stA(s);
            ldB(ch * 64, s); CP_COMMIT();
            if (ch < 63) ldA((ch + 1) * 64);
            cp_wait<0>();
            BAR_ARRIVE(1 + s, 384);
        }
        // -------- phase 2: 16 half-tiles of W --------
        for (int it = 0; it < 16; it++) {
            const int s = it & 1, op = it & 7, h = it >> 3;
            BAR_SYNC(3 + s, 384);
            uint32_t wh = sb + s * 65536;
            uint32_t wl = wh + 16384;
#pragma unroll
            for (int i = 0; i < 8; i++) {
                int idx = ptid + i * 128;
                int r = idx >> 4, c16 = idx & 15;
                uint32_t so = r * 256 + ((uint32_t)(c16 ^ (r & 7)) << 4);
                CP16(wh + so, &g_wTh[(size_t)op * 16384 + (h * 64 + r) * C_DIM + c16 * 8]);
                CP16(wl + so, &g_wTl[(size_t)op * 16384 + (h * 64 + r) * C_DIM + c16 * 8]);
            }
            CP_COMMIT(); cp_wait<0>();
            BAR_ARRIVE(1 + s, 384);
        }
        // -------- phase 3: 32 write_w n-tiles --------
        for (int nt = 0; nt < 32; nt++) {
            const int s = nt & 1;
            BAR_SYNC(3 + s, 384);
            uint32_t bh = sb + s * 65536;
            uint32_t bl = bh + 32768;
            const int n0 = nt * 128;
#pragma unroll
            for (int i = 0; i < 16; i++) {
                int idx = ptid + i * 128;
                int r = idx >> 4, c16 = idx & 15;
                uint32_t so = r * 256 + ((uint32_t)(c16 ^ (r & 7)) << 4);
                CP16(bh + so, &g_wwh[(size_t)(n0 + r) * C_DIM + c16 * 8]);
                CP16(bl + so, &g_wwl[(size_t)(n0 + r) * C_DIM + c16 * 8]);
            }
            CP_COMMIT(); cp_wait<0>();
            BAR_ARRIVE(1 + s, 384);
        }
        return;
    }

    // ==================== CONSUMER PATH (warps 0-7) ====================
    const int wr = wid & 3, wc = wid >> 2;   // 4x2, tile 32x64
    const int arow16 = lane & 15;
    const int ako = lane >> 4;
    const int brow8 = ((lane >> 4) & 1) * 8 + (lane & 7);
    const int bko = (lane >> 3) & 1;

    // bias + logit softmax (consumers only)
#pragma unroll
    for (int i = 0; i < 4; i++) bs[tid + i * 256] = bias[tid + i * 256];
    float wv[N_OPS];
    float mx = -1e30f;
#pragma unroll
    for (int i = 0; i < N_OPS; i++) { wv[i] = __ldg(&logits[i]); mx = fmaxf(mx, wv[i]); }
    float sumw = 0.0f;
#pragma unroll
    for (int i = 0; i < N_OPS; i++) { wv[i] = expf(wv[i] - mx); sumw += wv[i]; }
#pragma unroll
    for (int i = 0; i < N_OPS; i++) wv[i] /= sumw;

    // ============ phase 1: values = x @ read_w ============
    {
        float acc[2][8][4];
#pragma unroll
        for (int a = 0; a < 2; a++)
#pragma unroll
            for (int b = 0; b < 8; b++)
#pragma unroll
                for (int c = 0; c < 4; c++) acc[a][b][c] = 0.0f;

        for (int ch = 0; ch < 64; ch++) {
            const int s = ch & 1;
            BAR_SYNC(1 + s, 384);
            const uint32_t ah0 = sb + s * 65536;
            const uint32_t al0 = ah0 + 16384;
            const uint32_t bh0 = ah0 + 32768;
            const uint32_t bl0 = ah0 + 49152;
#pragma unroll
            for (int ks = 0; ks < 4; ks++) {
                uint32_t Ah[2][4], Al[2][4];
#pragma unroll
                for (int mf = 0; mf < 2; mf++) {
                    uint32_t rr = wr * 32 + mf * 16 + arow16;
                    uint32_t so = rr * 128 + ((uint32_t)((ks * 2 + ako) ^ (rr & 7)) << 4);
                    ldsm4(Ah[mf][0], Ah[mf][1], Ah[mf][2], Ah[mf][3], ah0 + so);
                    ldsm4(Al[mf][0], Al[mf][1], Al[mf][2], Al[mf][3], al0 + so);
                }
#pragma unroll
                for (int p = 0; p < 4; p++) {
                    uint32_t rr = wc * 64 + p * 16 + brow8;
                    uint32_t so = rr * 128 + ((uint32_t)((ks * 2 + bko) ^ (rr & 7)) << 4);
                    uint32_t Bh[2][2], Bl[2][2];
                    ldsm4(Bh[0][0], Bh[0][1], Bh[1][0], Bh[1][1], bh0 + so);
                    ldsm4(Bl[0][0], Bl[0][1], Bl[1][0], Bl[1][1], bl0 + so);
#pragma unroll
                    for (int mf = 0; mf < 2; mf++)
#pragma unroll
                        for (int q = 0; q < 2; q++) {
                            mma_bf16(acc[mf][2 * p + q], Ah[mf], Bh[q]);
                            mma_bf16(acc[mf][2 * p + q], Ah[mf], Bl[q]);
                            mma_bf16(acc[mf][2 * p + q], Al[mf], Bh[q]);
                        }
                }
            }
            BAR_ARRIVE(3 + s, 384);
        }

        // vals -> smem
#pragma unroll
        for (int mf = 0; mf < 2; mf++)
#pragma unroll
            for (int nf = 0; nf < 8; nf++) {
                int r = wr * 32 + mf * 16 + (lane >> 2);
                int c = wc * 64 + nf * 8 + 2 * (lane & 3);
                uint32_t h0, l0, h1, l1;
                split2(acc[mf][nf][0], acc[mf][nf][1], h0, l0);
                split2(acc[mf][nf][2], acc[mf][nf][3], h1, l1);
                uint32_t so0 = r * 256 + ((uint32_t)((c >> 3) ^ (r & 7)) << 4) + ((c & 7) << 1);
                uint32_t so1 = (r + 8) * 256 + ((uint32_t)((c >> 3) ^ ((r + 8) & 7)) << 4) + ((c & 7) << 1);
                *(uint32_t*)(sm + VH + so0) = h0;
                *(uint32_t*)(sm + VL + so0) = l0;
                *(uint32_t*)(sm + VH + so1) = h1;
                *(uint32_t*)(sm + VL + so1) = l1;
            }
        BAR_SYNC(5, 256);
    }

    // ============ phase 2: op bank (2 halves x 8 ops, tile 32x32) ============
    float resA[2][4][4], resB[2][4][4];
#pragma unroll
    for (int a = 0; a < 2; a++)
#pragma unroll
        for (int b = 0; b < 4; b++)
#pragma unroll
            for (int c = 0; c < 4; c++) { resA[a][b][c] = 0.0f; resB[a][b][c] = 0.0f; }

#pragma unroll 1
    for (int it = 0; it < 16; it++) {
        const int s = it & 1, op = it & 7, h = it >> 3;
        BAR_SYNC(1 + s, 384);

        float acc[2][4][4];
#pragma unroll
        for (int a = 0; a < 2; a++)
#pragma unroll
            for (int b = 0; b < 4; b++)
#pragma unroll
                for (int c = 0; c < 4; c++) acc[a][b][c] = 0.0f;

        const uint32_t wh0 = sb + s * 65536;
        const uint32_t wl0 = wh0 + 16384;
#pragma unroll
        for (int ks = 0; ks < 8; ks++) {
            uint32_t Ah[2][4], Al[2][4];
#pragma unroll
            for (int mf = 0; mf < 2; mf++) {
                uint32_t rr = wr * 32 + mf * 16 + arow16;
                uint32_t so = rr * 256 + ((uint32_t)((ks * 2 + ako) ^ (rr & 7)) << 4);
                ldsm4(Ah[mf][0], Ah[mf][1], Ah[mf][2], Ah[mf][3], sb + VH + so);
                ldsm4(Al[mf][0], Al[mf][1], Al[mf][2], Al[mf][3], sb + VL + so);
            }
#pragma unroll
            for (int p = 0; p < 2; p++) {
                uint32_t rr = wc * 32 + p * 16 + brow8;
                uint32_t so = rr * 256 + ((uint32_t)((ks * 2 + bko) ^ (rr & 7)) << 4);
                uint32_t Bh[2][2], Bl[2][2];
                ldsm4(Bh[0][0], Bh[0][1], Bh[1][0], Bh[1][1], wh0 + so);
                ldsm4(Bl[0][0], Bl[0][1], Bl[1][0], Bl[1][1], wl0 + so);
#pragma unroll
                for (int mf = 0; mf < 2; mf++)
#pragma unroll
                    for (int q = 0; q < 2; q++) {
                        mma_bf16(acc[mf][2 * p + q], Ah[mf], Bh[q]);
                        mma_bf16(acc[mf][2 * p + q], Ah[mf], Bl[q]);
                        mma_bf16(acc[mf][2 * p + q], Al[mf], Bh[q]);
                    }
            }
        }
        BAR_ARRIVE(3 + s, 384);

        const float w = wv[op];
        float (*res)[4][4] = h ? resB : resA;
#pragma unroll
        for (int mf = 0; mf < 2; mf++)
#pragma unroll
            for (int nf = 0; nf < 4; nf++)
#pragma unroll
                for (int j = 0; j < 4; j++) {
                    int col = h * 64 + wc * 32 + nf * 8 + 2 * (lane & 3) + (j & 1);
                    float v = acc[mf][nf][j] + bs[op * C_DIM + col];
                    float f;
                    switch (op) {
                        case 0: f = v; break;
                        case 1: f = fmaxf(v, 0.0f); break;
                        case 2: f = 0.5f * v * (1.0f + erff(v * 0.70710678118654752f)); break;
                        case 3: f = v * v; break;
                        case 4: f = -v; break;
                        case 5: f = fabsf(v); break;
                        case 6: f = tanhf(v); break;
                        default: f = 1.0f / (1.0f + expf(-v)); break;
                    }
                    res[mf][nf][j] += w * f;
                }
    }

    // mix -> smem (overwrite vals after ALL consumer reads)
    BAR_SYNC(5, 256);
#pragma unroll
    for (int h = 0; h < 2; h++)
#pragma unroll
        for (int mf = 0; mf < 2; mf++)
#pragma unroll
            for (int nf = 0; nf < 4; nf++) {
                float (*res)[4][4] = h ? resB : resA;
                int r = wr * 32 + mf * 16 + (lane >> 2);
                int c = h * 64 + wc * 32 + nf * 8 + 2 * (lane & 3);
                uint32_t h0, l0, h1, l1;
                split2(res[mf][nf][0], res[mf][nf][1], h0, l0);
                split2(res[mf][nf][2], res[mf][nf][3], h1, l1);
                uint32_t so0 = r * 256 + ((uint32_t)((c >> 3) ^ (r & 7)) << 4) + ((c & 7) << 1);
                uint32_t so1 = (r + 8) * 256 + ((uint32_t)((c >> 3) ^ ((r + 8) & 7)) << 4) + ((c & 7) << 1);
                *(uint32_t*)(sm + VH + so0) = h0;
                *(uint32_t*)(sm + VL + so0) = l0;
                *(uint32_t*)(sm + VH + so1) = h1;
                *(uint32_t*)(sm + VL + so1) = l1;
            }
    BAR_SYNC(5, 256);

    // ============ phase 3: out = mix @ write_w^T * alpha ============
    {
        const float alpha = __ldg(oscale);
#pragma unroll 1
        for (int nt = 0; nt < 32; nt++) {
            const int s = nt & 1;
            BAR_SYNC(1 + s, 384);

            float acc[2][8][4];
#pragma unroll
            for (int a = 0; a < 2; a++)
#pragma unroll
                for (int b = 0; b < 8; b++)
#pragma unroll
                    for (int c = 0; c < 4; c++) acc[a][b][c] = 0.0f;

            const uint32_t bh0 = sb + s * 65536;
            const uint32_t bl0 = bh0 + 32768;
#pragma unroll
            for (int ks = 0; ks < 8; ks++) {
                uint32_t Ah[2][4], Al[2][4];
#pragma unroll
                for (int mf = 0; mf < 2; mf++) {
                    uint32_t rr = wr * 32 + mf * 16 + arow16;
                    uint32_t so = rr * 256 + ((uint32_t)((ks * 2 + ako) ^ (rr & 7)) << 4);
                    ldsm4(Ah[mf][0], Ah[mf][1], Ah[mf][2], Ah[mf][3], sb + VH + so);
                    ldsm4(Al[mf][0], Al[mf][1], Al[mf][2], Al[mf][3], sb + VL + so);
                }
#pragma unroll
                for (int p = 0; p < 4; p++) {
                    uint32_t rr = wc * 64 + p * 16 + brow8;
                    uint32_t so = rr * 256 + ((uint32_t)((ks * 2 + bko) ^ (rr & 7)) << 4);
                    uint32_t Bh[2][2], Bl[2][2];
                    ldsm4(Bh[0][0], Bh[0][1], Bh[1][0], Bh[1][1], bh0 + so);
                    ldsm4(Bl[0][0], Bl[0][1], Bl[1][0], Bl[1][1], bl0 + so);
#pragma unroll
                    for (int mf = 0; mf < 2; mf++)
#pragma unroll
                        for (int q = 0; q < 2; q++) {
                            mma_bf16(acc[mf][2 * p + q], Ah[mf], Bh[q]);
                            mma_bf16(acc[mf][2 * p + q], Ah[mf], Bl[q]);
                            mma_bf16(acc[mf][2 * p + q], Al[mf], Bh[q]);
                        }
                }
            }
            BAR_ARRIVE(3 + s, 384);

#pragma unroll
            for (int mf = 0; mf < 2; mf++)
#pragma unroll
                for (int nf = 0; nf < 8; nf++) {
                    int r = m0 + wr * 32 + mf * 16 + (lane >> 2);
                    int c = nt * 128 + wc * 64 + nf * 8 + 2 * (lane & 3);
                    float2 v0 = make_float2(acc[mf][nf][0] * alpha, acc[mf][nf][1] * alpha);
                    float2 v1 = make_float2(acc[mf][nf][2] * alpha, acc[mf][nf][3] * alpha);
                    *(float2*)&out[(size_t)r * V_DIM + c] = v0;
                    *(float2*)&out[(size_t)(r + 8) * V_DIM + c] = v1;
                }
        }
    }
}

// ---------------------------------------------------------------------------
extern "C" void kernel_launch(void* const* d_in, const int* in_sizes, int n_in,
                              void* d_out, int out_size)
{
    const float* x      = (const float*)d_in[0];
    const float* basis  = (const float*)d_in[1];
    const float* rcoef  = (const float*)d_in[2];
    const float* wcoef  = (const float*)d_in[3];
    const float* logits = (const float*)d_in[4];
    const float* opW    = (const float*)d_in[5];
    const float* opB    = (const float*)d_in[6];
    const float* oscale = (const float*)d_in[7];
    float* out = (float*)d_out;

    float* p_rw;
    cudaGetSymbolAddress((void**)&p_rw, g_rw);

    static bool attr_done = false;
    if (!attr_done) {
        cudaFuncSetAttribute(mega, cudaFuncAttributeMaxDynamicSharedMemorySize, 196608);
        attr_done = true;
    }

    sgemm_addr<<<dim3(1, V_DIM / 128, 2), 256>>>(basis, rcoef, wcoef);
    col_softmax_T<<<C_DIM, 256>>>(p_rw);
    prep_wT<<<N_OPS * C_DIM * C_DIM / 256, 256>>>(opW);
    mega<<<M_TOK / 128, 384, 196608>>>(x, logits, opB, out, oscale);
}